// round 4
// baseline (speedup 1.0000x reference)
#include <cuda_runtime.h>

#define DD 128
#define MAXN 50000
#define MAXE 600000
#define GG 64

// ---------------- scratch (static device globals; no runtime allocation) ----
__device__ float g_agg[MAXN * DD];
__device__ float g_h0[MAXN * DD];
__device__ float g_h1[MAXN * DD];
__device__ int   g_deg[MAXN];
__device__ int   g_off[MAXN + 1];
__device__ int   g_cur[MAXN];
__device__ int   g_csr[MAXE];
__device__ int   g_src[MAXE];
__device__ int   g_dst[MAXE];
__device__ int   g_batch[MAXN];
__device__ int   g_gstart[GG + 1];
__device__ float g_pool[GG * DD];
__device__ int   g_e32;   // 1 if edge_index is int32, 0 if int64
__device__ int   g_b32;   // 1 if batch is int32, 0 if int64

// ---------------- preprocessing ---------------------------------------------

__global__ void k_init(int N) {
    int i = blockIdx.x * blockDim.x + threadIdx.x;
    if (i < N) g_deg[i] = 0;
    if (i == 0) { g_e32 = 0; g_b32 = 0; }
}

// If the raw buffer holds little-endian int64 of small nonneg values, every
// odd 32-bit word is 0. If it holds int32, odd words are real (mostly
// nonzero) values. Benign-race stores of 1 to the flag.
__global__ void k_detect(const int* __restrict__ raw, int npairs, int which) {
    int i = blockIdx.x * blockDim.x + threadIdx.x;
    if (i >= npairs) return;
    if (raw[2 * i + 1] != 0) {
        if (which) g_b32 = 1; else g_e32 = 1;
    }
}

__global__ void k_conv_edges(const int* __restrict__ raw, int E) {
    int e = blockIdx.x * blockDim.x + threadIdx.x;
    if (e >= E) return;
    if (g_e32) { g_src[e] = raw[e];     g_dst[e] = raw[E + e]; }
    else       { g_src[e] = raw[2 * e]; g_dst[e] = raw[2 * (E + e)]; }
}

__global__ void k_conv_batch(const int* __restrict__ raw, int N) {
    int i = blockIdx.x * blockDim.x + threadIdx.x;
    if (i >= N) return;
    g_batch[i] = g_b32 ? raw[i] : raw[2 * i];
}

__global__ void k_hist(int E) {
    int e = blockIdx.x * blockDim.x + threadIdx.x;
    if (e < E) atomicAdd(&g_deg[g_dst[e]], 1);
}

// single-block exclusive scan of g_deg -> g_off (off[0]=0), g_cur = off copy
__global__ void k_scan(int N) {
    __shared__ int sw[32];
    const int tid  = threadIdx.x;
    const int lane = tid & 31;
    const int w    = tid >> 5;
    int carry = 0;
    if (tid == 0) g_off[0] = 0;
    for (int base = 0; base < N; base += 1024) {
        int i = base + tid;
        int v = (i < N) ? g_deg[i] : 0;
        int x = v;
#pragma unroll
        for (int d = 1; d < 32; d <<= 1) {
            int t = __shfl_up_sync(0xffffffffu, x, d);
            if (lane >= d) x += t;
        }
        if (lane == 31) sw[w] = x;
        __syncthreads();
        if (w == 0) {
            int y = sw[lane];
#pragma unroll
            for (int d = 1; d < 32; d <<= 1) {
                int t = __shfl_up_sync(0xffffffffu, y, d);
                if (lane >= d) y += t;
            }
            sw[lane] = y;
        }
        __syncthreads();
        int add = (w > 0) ? sw[w - 1] : 0;
        x += add + carry;
        if (i < N) { g_off[i + 1] = x; g_cur[i] = x - v; }
        int total = sw[31];
        __syncthreads();
        carry += total;
    }
}

__global__ void k_fill(int E) {
    int e = blockIdx.x * blockDim.x + threadIdx.x;
    if (e >= E) return;
    int p = atomicAdd(&g_cur[g_dst[e]], 1);
    g_csr[p] = g_src[e];
}

// graph segment boundaries from sorted batch
__global__ void k_bounds(int N, int G) {
    int i = blockIdx.x * blockDim.x + threadIdx.x;
    if (i >= N) return;
    int b = g_batch[i];
    if (i == 0) {
        for (int g = 0; g <= b; ++g) g_gstart[g] = 0;
    } else {
        int pb = g_batch[i - 1];
        for (int g = pb + 1; g <= b; ++g) g_gstart[g] = i;
    }
    if (i == N - 1) {
        for (int g = b + 1; g <= G; ++g) g_gstart[g] = N;
    }
}

// ---------------- layer kernels ---------------------------------------------

// One warp per node: sum h[src] over incoming edges. One float4 per lane.
__global__ void k_gather(const float* __restrict__ xin, int sel, int N) {
    int warp = (blockIdx.x * blockDim.x + threadIdx.x) >> 5;
    int lane = threadIdx.x & 31;
    if (warp >= N) return;
    const float* H = (sel == 0) ? xin : (sel == 1 ? g_h0 : g_h1);
    int s = g_off[warp], e = g_off[warp + 1];
    float4 acc = make_float4(0.f, 0.f, 0.f, 0.f);
    for (int i = s; i < e; ++i) {
        int src = g_csr[i];
        float4 v = reinterpret_cast<const float4*>(H)[src * 32 + lane];
        acc.x += v.x; acc.y += v.y; acc.z += v.z; acc.w += v.w;
    }
    reinterpret_cast<float4*>(g_agg)[warp * 32 + lane] = acc;
}

// Fused dual GEMM: out = agg @ Wrel^T + h @ Wroot^T + brel, optional relu.
// 128x128 tile per block, 256 threads, 8x8 micro-tile, f32x2 packed FMA.
// Smem: both W matrices k-major with 132-float row pad, A chunk transposed.
__global__ void __launch_bounds__(256, 1) k_gemm(
    const float* __restrict__ xin, int selIn, int selOut,
    const float* __restrict__ Wrel, const float* __restrict__ Wroot,
    const float* __restrict__ brel, int N, int do_relu)
{
    extern __shared__ float sm[];
    float* Ws = sm;                   // [2*128][132]  (k-major: Ws[k][n])
    float* As = sm + 2 * 128 * 132;   // [16][132]     (k-major: As[k][m])

    const int tid  = threadIdx.x;
    const int tm   = tid >> 4;        // 0..15 -> rows tm*8..tm*8+7
    const int tn   = tid & 15;        // 0..15 -> cols tn*8..tn*8+7
    const int row0 = blockIdx.x * 128;

    const float* Ain   = (selIn == 0) ? xin : (selIn == 1 ? g_h0 : g_h1);
    float*       Hout  = (selOut == 1) ? g_h0 : g_h1;

    // load both weight matrices into smem, transposed to k-major
    for (int idx = tid; idx < 128 * 128; idx += 256) {
        int n = idx >> 7, k = idx & 127;
        Ws[k * 132 + n]         = Wrel[idx];
        Ws[(128 + k) * 132 + n] = Wroot[idx];
    }

    unsigned long long acc[8][4];
#pragma unroll
    for (int i = 0; i < 8; ++i)
#pragma unroll
        for (int j = 0; j < 4; ++j) acc[i][j] = 0ull;

#pragma unroll 1
    for (int pass = 0; pass < 2; ++pass) {
        const float* A = pass ? Ain : g_agg;
#pragma unroll 1
        for (int k0 = 0; k0 < 128; k0 += 16) {
            __syncthreads();
            // stage A chunk [rows 0..127][k0..k0+15] transposed into As[k][m]
#pragma unroll
            for (int t = 0; t < 2; ++t) {
                int i = tid * 2 + t;
                int m = i >> 2, q = i & 3;
                int row = row0 + m;
                float4 v = make_float4(0.f, 0.f, 0.f, 0.f);
                if (row < N)
                    v = reinterpret_cast<const float4*>(A)[row * 32 + (k0 >> 2) + q];
                As[(q * 4 + 0) * 132 + m] = v.x;
                As[(q * 4 + 1) * 132 + m] = v.y;
                As[(q * 4 + 2) * 132 + m] = v.z;
                As[(q * 4 + 3) * 132 + m] = v.w;
            }
            __syncthreads();
            const float* Wb = Ws + (pass * 128 + k0) * 132 + tn * 8;
            const float* Ab = As + tm * 8;
#pragma unroll
            for (int kk = 0; kk < 16; ++kk) {
                float a[8];
                *reinterpret_cast<float4*>(a)     = *reinterpret_cast<const float4*>(Ab + kk * 132);
                *reinterpret_cast<float4*>(a + 4) = *reinterpret_cast<const float4*>(Ab + kk * 132 + 4);
                ulonglong2 bA = *reinterpret_cast<const ulonglong2*>(Wb + kk * 132);
                ulonglong2 bB = *reinterpret_cast<const ulonglong2*>(Wb + kk * 132 + 4);
                unsigned long long b2[4] = { bA.x, bA.y, bB.x, bB.y };
#pragma unroll
                for (int i = 0; i < 8; ++i) {
                    unsigned long long a2;
                    asm("mov.b64 %0, {%1, %1};" : "=l"(a2) : "f"(a[i]));
#pragma unroll
                    for (int j = 0; j < 4; ++j)
                        asm("fma.rn.f32x2 %0, %1, %2, %0;"
                            : "+l"(acc[i][j]) : "l"(a2), "l"(b2[j]));
                }
            }
        }
    }

    float bias[8];
    *reinterpret_cast<float4*>(bias)     = *reinterpret_cast<const float4*>(brel + tn * 8);
    *reinterpret_cast<float4*>(bias + 4) = *reinterpret_cast<const float4*>(brel + tn * 8 + 4);

#pragma unroll
    for (int i = 0; i < 8; ++i) {
        int row = row0 + tm * 8 + i;
        if (row >= N) continue;
        float o[8];
#pragma unroll
        for (int j = 0; j < 4; ++j) {
            float lo, hi;
            asm("mov.b64 {%0, %1}, %2;" : "=f"(lo), "=f"(hi) : "l"(acc[i][j]));
            o[2 * j]     = lo + bias[2 * j];
            o[2 * j + 1] = hi + bias[2 * j + 1];
        }
        if (do_relu) {
#pragma unroll
            for (int j = 0; j < 8; ++j) o[j] = fmaxf(o[j], 0.f);
        }
        float4* dst = reinterpret_cast<float4*>(Hout + (long)row * 128 + tn * 8);
        dst[0] = *reinterpret_cast<float4*>(o);
        dst[1] = *reinterpret_cast<float4*>(o + 4);
    }
}

// ---------------- pooling + MLP ---------------------------------------------

// block per (graph, 32-col chunk): deterministic segment max over g_h0
__global__ void k_pool() {
    int g     = blockIdx.x;
    int chunk = blockIdx.y;
    int lane  = threadIdx.x & 31;
    int grp   = threadIdx.x >> 5;   // 0..7
    int col   = chunk * 32 + lane;
    int s = g_gstart[g], e = g_gstart[g + 1];
    float m = -3.402823466e38f;
    for (int r = s + grp; r < e; r += 8)
        m = fmaxf(m, g_h0[(long)r * 128 + col]);
    __shared__ float smx[8][32];
    smx[grp][lane] = m;
    __syncthreads();
    if (grp == 0) {
#pragma unroll
        for (int i = 1; i < 8; ++i) m = fmaxf(m, smx[i][lane]);
        g_pool[g * 128 + col] = m;
    }
}

__global__ void k_mlp(const float* __restrict__ W1, const float* __restrict__ b1,
                      const float* __restrict__ W2, const float* __restrict__ b2,
                      float* __restrict__ out, int G) {
    int g = threadIdx.x;
    if (g >= G) return;
    float o = b2[0];
#pragma unroll
    for (int j = 0; j < 5; ++j) {
        float s = b1[j];
        for (int k = 0; k < DD; k += 4) {
            float4 p  = reinterpret_cast<const float4*>(g_pool + g * DD)[k >> 2];
            float4 ww = reinterpret_cast<const float4*>(W1 + j * DD)[k >> 2];
            s += p.x * ww.x + p.y * ww.y + p.z * ww.z + p.w * ww.w;
        }
        o += fmaxf(s, 0.f) * W2[j];
    }
    out[g] = o;
}

// ---------------- launch -----------------------------------------------------

extern "C" void kernel_launch(void* const* d_in, const int* in_sizes, int n_in,
                              void* d_out, int out_size) {
    const float* x    = (const float*)d_in[0];
    const int*   eraw = (const int*)d_in[1];
    const int*   braw = (const int*)d_in[2];
    const float* Wr1  = (const float*)d_in[3];
    const float* br1  = (const float*)d_in[4];
    const float* Wo1  = (const float*)d_in[5];
    const float* Wr2  = (const float*)d_in[6];
    const float* br2  = (const float*)d_in[7];
    const float* Wo2  = (const float*)d_in[8];
    const float* Wr3  = (const float*)d_in[9];
    const float* br3  = (const float*)d_in[10];
    const float* Wo3  = (const float*)d_in[11];
    const float* W1   = (const float*)d_in[12];
    const float* b1   = (const float*)d_in[13];
    const float* W2   = (const float*)d_in[14];
    const float* b2   = (const float*)d_in[15];
    float* out = (float*)d_out;

    const int N = in_sizes[0] / DD;
    const int E = in_sizes[1] / 2;
    const int G = out_size;

    const int nb = (N + 255) / 256;
    const int eb = (E + 255) / 256;

    // CSR + batch preprocessing (rebuilt every call; deterministic work)
    k_init<<<nb, 256>>>(N);
    k_detect<<<eb, 256>>>(eraw, E, 0);
    k_detect<<<(N / 2 + 255) / 256, 256>>>(braw, N / 2, 1);
    k_conv_edges<<<eb, 256>>>(eraw, E);
    k_conv_batch<<<nb, 256>>>(braw, N);
    k_hist<<<eb, 256>>>(E);
    k_scan<<<1, 1024>>>(N);
    k_fill<<<eb, 256>>>(E);
    k_bounds<<<nb, 256>>>(N, G);

    const size_t smem = (size_t)(2 * 128 * 132 + 16 * 132) * sizeof(float);
    cudaFuncSetAttribute(k_gemm, cudaFuncAttributeMaxDynamicSharedMemorySize,
                         (int)smem);

    const int gw = (N + 7) / 8;        // gather: 8 warps/block
    const int gb = (N + 127) / 128;    // gemm tiles

    // layer 1: in = x (sel 0), out = h0 (sel 1), relu
    k_gather<<<gw, 256>>>(x, 0, N);
    k_gemm<<<gb, 256, smem>>>(x, 0, 1, Wr1, Wo1, br1, N, 1);
    // layer 2: in = h0, out = h1, relu
    k_gather<<<gw, 256>>>(x, 1, N);
    k_gemm<<<gb, 256, smem>>>(x, 1, 2, Wr2, Wo2, br2, N, 1);
    // layer 3: in = h1, out = h0, no relu
    k_gather<<<gw, 256>>>(x, 2, N);
    k_gemm<<<gb, 256, smem>>>(x, 2, 1, Wr3, Wo3, br3, N, 0);

    dim3 pg(G, DD / 32);
    k_pool<<<pg, 256>>>();
    k_mlp<<<1, 64>>>(W1, b1, W2, b2, out, G);
}

// round 5
// speedup vs baseline: 1.1273x; 1.1273x over previous
#include <cuda_runtime.h>

#define DD 128
#define MAXN 50000
#define MAXE 600000
#define GG 64

// ---------------- scratch (static device globals; no runtime allocation) ----
__device__ float g_agg[MAXN * DD];
__device__ float g_h0[MAXN * DD];
__device__ float g_h1[MAXN * DD];
__device__ int   g_deg[MAXN];
__device__ int   g_off[MAXN + 1];
__device__ int   g_cur[MAXN];
__device__ int   g_csr[MAXE];
__device__ int   g_src[MAXE];
__device__ int   g_dst[MAXE];
__device__ int   g_gstart[GG + 1];
__device__ float g_pool[GG * DD];
__device__ int   g_e32;       // 1 if edge_index is int32, 0 if int64
__device__ int   g_b32;       // 1 if batch is int32, 0 if int64
__device__ int   g_bsum[64];  // block partial sums for the scan

// ---------------- preprocessing ---------------------------------------------

__global__ void k_init(int N) {
    int i = blockIdx.x * blockDim.x + threadIdx.x;
    if (i < N) g_deg[i] = 0;
    if (i == 0) { g_e32 = 0; g_b32 = 0; }
}

// Strided sampling: int64 nonneg values have all odd 32-bit words zero.
// 1024 samples spread over the array; int32 data has nonzero odd words.
__global__ void k_detect(const int* __restrict__ raw, int npairs, int which) {
    long idx = ((long)threadIdx.x * npairs) >> 10;
    if (idx < npairs && raw[2 * idx + 1] != 0) {
        if (which) g_b32 = 1; else g_e32 = 1;
    }
}

// convert edges + degree histogram (fused)
__global__ void k_edges(const int* __restrict__ raw, int E) {
    int e = blockIdx.x * blockDim.x + threadIdx.x;
    if (e >= E) return;
    int s, d;
    if (g_e32) { s = raw[e];     d = raw[E + e]; }
    else       { s = raw[2 * e]; d = raw[2 * (E + e)]; }
    g_src[e] = s;
    g_dst[e] = d;
    atomicAdd(&g_deg[d], 1);
}

// convert batch + graph boundaries (fused; batch is sorted)
__global__ void k_batch(const int* __restrict__ raw, int N, int G) {
    int i = blockIdx.x * blockDim.x + threadIdx.x;
    if (i >= N) return;
    int b  = g_b32 ? raw[i] : raw[2 * i];
    int pb = (i == 0) ? -1 : (g_b32 ? raw[i - 1] : raw[2 * (i - 1)]);
    for (int g = pb + 1; g <= b; ++g) g_gstart[g] = i;
    if (i == N - 1)
        for (int g = b + 1; g <= G; ++g) g_gstart[g] = N;
}

// scan phase 1: per-1024-block reduction of g_deg -> g_bsum
__global__ void k_scan1(int N) {
    __shared__ int sw[32];
    int tid = threadIdx.x, lane = tid & 31, w = tid >> 5;
    int i = blockIdx.x * 1024 + tid;
    int v = (i < N) ? g_deg[i] : 0;
#pragma unroll
    for (int d = 16; d > 0; d >>= 1) v += __shfl_down_sync(0xffffffffu, v, d);
    if (lane == 0) sw[w] = v;
    __syncthreads();
    if (w == 0) {
        v = sw[lane];
#pragma unroll
        for (int d = 16; d > 0; d >>= 1) v += __shfl_down_sync(0xffffffffu, v, d);
        if (lane == 0) g_bsum[blockIdx.x] = v;
    }
}

// scan phase 2: exclusive scan of the (<=64) block sums, trivial serial
__global__ void k_scan2(int nsb) {
    if (threadIdx.x == 0) {
        int a = 0;
        for (int b = 0; b < nsb; ++b) { int t = g_bsum[b]; g_bsum[b] = a; a += t; }
    }
}

// scan phase 3: per-block inclusive scan + base -> g_off / g_cur
__global__ void k_scan3(int N) {
    __shared__ int sw[32];
    int tid = threadIdx.x, lane = tid & 31, w = tid >> 5;
    int i = blockIdx.x * 1024 + tid;
    int v = (i < N) ? g_deg[i] : 0;
    int x = v;
#pragma unroll
    for (int d = 1; d < 32; d <<= 1) {
        int t = __shfl_up_sync(0xffffffffu, x, d);
        if (lane >= d) x += t;
    }
    if (lane == 31) sw[w] = x;
    __syncthreads();
    if (w == 0) {
        int y = sw[lane];
#pragma unroll
        for (int d = 1; d < 32; d <<= 1) {
            int t = __shfl_up_sync(0xffffffffu, y, d);
            if (lane >= d) y += t;
        }
        sw[lane] = y;
    }
    __syncthreads();
    x += ((w > 0) ? sw[w - 1] : 0) + g_bsum[blockIdx.x];
    if (i < N) { g_off[i + 1] = x; g_cur[i] = x - v; }
    if (i == 0) g_off[0] = 0;
}

__global__ void k_fill(int E) {
    int e = blockIdx.x * blockDim.x + threadIdx.x;
    if (e >= E) return;
    int p = atomicAdd(&g_cur[g_dst[e]], 1);
    g_csr[p] = g_src[e];
}

// ---------------- layer kernels ---------------------------------------------

// One warp per node: sum h[src] over incoming edges, 2-edge unrolled.
__global__ void k_gather(const float* __restrict__ xin, int sel, int N) {
    int warp = (blockIdx.x * blockDim.x + threadIdx.x) >> 5;
    int lane = threadIdx.x & 31;
    if (warp >= N) return;
    const float* H = (sel == 0) ? xin : (sel == 1 ? g_h0 : g_h1);
    const float4* H4 = reinterpret_cast<const float4*>(H);
    int s = g_off[warp], e = g_off[warp + 1];
    float4 acc = make_float4(0.f, 0.f, 0.f, 0.f);
    int i = s;
    for (; i + 2 <= e; i += 2) {
        int s0 = g_csr[i], s1 = g_csr[i + 1];
        float4 v0 = H4[s0 * 32 + lane];
        float4 v1 = H4[s1 * 32 + lane];
        acc.x += v0.x + v1.x; acc.y += v0.y + v1.y;
        acc.z += v0.z + v1.z; acc.w += v0.w + v1.w;
    }
    if (i < e) {
        float4 v = H4[g_csr[i] * 32 + lane];
        acc.x += v.x; acc.y += v.y; acc.z += v.z; acc.w += v.w;
    }
    reinterpret_cast<float4*>(g_agg)[warp * 32 + lane] = acc;
}

// Single-W GEMM: out = A @ W^T (+bias) (+= existing) (relu), 128x128 tile,
// 256 threads, 8x8 micro, f32x2 packed FMA, double-buffered A staging.
// smem: Ws[128][132] k-major + As[2][16][132] => 84480 B => 2 CTAs/SM.
__global__ void __launch_bounds__(256, 2) k_gemm(
    const float* __restrict__ xin, int selIn, int selOut,
    const float* __restrict__ W, const float* __restrict__ bias,
    int N, int accumulate, int do_relu)
{
    extern __shared__ float sm[];
    float* Ws = sm;                 // [128][132] k-major: Ws[k*132+n]
    float* As = sm + 128 * 132;     // [2][16][132] k-major: As[buf][k][m]

    const int tid  = threadIdx.x;
    const int tm   = tid >> 4;
    const int tn   = tid & 15;
    const int row0 = blockIdx.x * 128;

    const float* Ain =
        (selIn == 0) ? xin : (selIn == 1 ? g_h0 : (selIn == 2 ? g_h1 : g_agg));
    float* Hout = (selOut == 1) ? g_h0 : g_h1;
    const float4* A4 = reinterpret_cast<const float4*>(Ain);

    // load W into smem, transposed to k-major
    for (int idx = tid; idx < 128 * 128; idx += 256) {
        int n = idx >> 7, k = idx & 127;
        Ws[k * 132 + n] = W[idx];
    }

    unsigned long long acc[8][4];
#pragma unroll
    for (int i = 0; i < 8; ++i)
#pragma unroll
        for (int j = 0; j < 4; ++j) acc[i][j] = 0ull;

    auto stage = [&](int buf, int c) {
        float* dst = As + buf * (16 * 132);
        int k0 = c * 16;
#pragma unroll
        for (int t = 0; t < 2; ++t) {
            int i = tid * 2 + t;
            int m = i >> 2, q = i & 3;
            int row = row0 + m;
            float4 v = make_float4(0.f, 0.f, 0.f, 0.f);
            if (row < N) v = A4[row * 32 + (k0 >> 2) + q];
            dst[(q * 4 + 0) * 132 + m] = v.x;
            dst[(q * 4 + 1) * 132 + m] = v.y;
            dst[(q * 4 + 2) * 132 + m] = v.z;
            dst[(q * 4 + 3) * 132 + m] = v.w;
        }
    };

    stage(0, 0);
    __syncthreads();

#pragma unroll 1
    for (int c = 0; c < 8; ++c) {
        int buf = c & 1;
        if (c < 7) stage(buf ^ 1, c + 1);   // prefetch next chunk
        const float* Wb = Ws + (c * 16) * 132 + tn * 8;
        const float* Ab = As + buf * (16 * 132) + tm * 8;
#pragma unroll
        for (int kk = 0; kk < 16; ++kk) {
            float a[8];
            *reinterpret_cast<float4*>(a)     = *reinterpret_cast<const float4*>(Ab + kk * 132);
            *reinterpret_cast<float4*>(a + 4) = *reinterpret_cast<const float4*>(Ab + kk * 132 + 4);
            ulonglong2 bA = *reinterpret_cast<const ulonglong2*>(Wb + kk * 132);
            ulonglong2 bB = *reinterpret_cast<const ulonglong2*>(Wb + kk * 132 + 4);
            unsigned long long b2[4] = { bA.x, bA.y, bB.x, bB.y };
#pragma unroll
            for (int i = 0; i < 8; ++i) {
                unsigned long long a2;
                asm("mov.b64 %0, {%1, %1};" : "=l"(a2) : "f"(a[i]));
#pragma unroll
                for (int j = 0; j < 4; ++j)
                    asm("fma.rn.f32x2 %0, %1, %2, %0;"
                        : "+l"(acc[i][j]) : "l"(a2), "l"(b2[j]));
            }
        }
        __syncthreads();
    }

    float bv[8];
    if (bias) {
        *reinterpret_cast<float4*>(bv)     = *reinterpret_cast<const float4*>(bias + tn * 8);
        *reinterpret_cast<float4*>(bv + 4) = *reinterpret_cast<const float4*>(bias + tn * 8 + 4);
    } else {
#pragma unroll
        for (int j = 0; j < 8; ++j) bv[j] = 0.f;
    }

#pragma unroll
    for (int i = 0; i < 8; ++i) {
        int row = row0 + tm * 8 + i;
        if (row >= N) continue;
        float o[8];
#pragma unroll
        for (int j = 0; j < 4; ++j) {
            float lo, hi;
            asm("mov.b64 {%0, %1}, %2;" : "=f"(lo), "=f"(hi) : "l"(acc[i][j]));
            o[2 * j]     = lo + bv[2 * j];
            o[2 * j + 1] = hi + bv[2 * j + 1];
        }
        float4* dst = reinterpret_cast<float4*>(Hout + (long)row * 128 + tn * 8);
        if (accumulate) {
            float4 p0 = dst[0], p1 = dst[1];
            o[0] += p0.x; o[1] += p0.y; o[2] += p0.z; o[3] += p0.w;
            o[4] += p1.x; o[5] += p1.y; o[6] += p1.z; o[7] += p1.w;
        }
        if (do_relu) {
#pragma unroll
            for (int j = 0; j < 8; ++j) o[j] = fmaxf(o[j], 0.f);
        }
        dst[0] = *reinterpret_cast<float4*>(o);
        dst[1] = *reinterpret_cast<float4*>(o + 4);
    }
}

// ---------------- pooling + MLP ---------------------------------------------

__global__ void k_pool() {
    int g     = blockIdx.x;
    int chunk = blockIdx.y;
    int lane  = threadIdx.x & 31;
    int grp   = threadIdx.x >> 5;
    int col   = chunk * 32 + lane;
    int s = g_gstart[g], e = g_gstart[g + 1];
    float m = -3.402823466e38f;
    for (int r = s + grp; r < e; r += 8)
        m = fmaxf(m, g_h0[(long)r * 128 + col]);
    __shared__ float smx[8][32];
    smx[grp][lane] = m;
    __syncthreads();
    if (grp == 0) {
#pragma unroll
        for (int i = 1; i < 8; ++i) m = fmaxf(m, smx[i][lane]);
        g_pool[g * 128 + col] = m;
    }
}

__global__ void k_mlp(const float* __restrict__ W1, const float* __restrict__ b1,
                      const float* __restrict__ W2, const float* __restrict__ b2,
                      float* __restrict__ out, int G) {
    int g = threadIdx.x;
    if (g >= G) return;
    float o = b2[0];
#pragma unroll
    for (int j = 0; j < 5; ++j) {
        float s = b1[j];
        for (int k = 0; k < DD; k += 4) {
            float4 p  = reinterpret_cast<const float4*>(g_pool + g * DD)[k >> 2];
            float4 ww = reinterpret_cast<const float4*>(W1 + j * DD)[k >> 2];
            s += p.x * ww.x + p.y * ww.y + p.z * ww.z + p.w * ww.w;
        }
        o += fmaxf(s, 0.f) * W2[j];
    }
    out[g] = o;
}

// ---------------- launch -----------------------------------------------------

extern "C" void kernel_launch(void* const* d_in, const int* in_sizes, int n_in,
                              void* d_out, int out_size) {
    const float* x    = (const float*)d_in[0];
    const int*   eraw = (const int*)d_in[1];
    const int*   braw = (const int*)d_in[2];
    const float* Wr1  = (const float*)d_in[3];
    const float* br1  = (const float*)d_in[4];
    const float* Wo1  = (const float*)d_in[5];
    const float* Wr2  = (const float*)d_in[6];
    const float* br2  = (const float*)d_in[7];
    const float* Wo2  = (const float*)d_in[8];
    const float* Wr3  = (const float*)d_in[9];
    const float* br3  = (const float*)d_in[10];
    const float* Wo3  = (const float*)d_in[11];
    const float* W1   = (const float*)d_in[12];
    const float* b1   = (const float*)d_in[13];
    const float* W2   = (const float*)d_in[14];
    const float* b2   = (const float*)d_in[15];
    float* out = (float*)d_out;

    const int N = in_sizes[0] / DD;
    const int E = in_sizes[1] / 2;
    const int G = out_size;

    const int nb  = (N + 255) / 256;
    const int eb  = (E + 255) / 256;
    const int nsb = (N + 1023) / 1024;
    const int gw  = (N + 7) / 8;
    const int gb  = (N + 127) / 128;

    const size_t SMEMSZ = (size_t)(128 * 132 + 2 * 16 * 132) * sizeof(float);
    cudaFuncSetAttribute(k_gemm, cudaFuncAttributeMaxDynamicSharedMemorySize,
                         (int)SMEMSZ);

    // Second stream + events, created once (outside capture on the first,
    // non-captured correctness call). Work is identical on every call.
    static cudaStream_t s2 = nullptr;
    static cudaEvent_t evFork, evRoot1, evRoot2, evRoot3, evL1, evL2;
    if (!s2) {
        cudaStreamCreateWithFlags(&s2, cudaStreamNonBlocking);
        cudaEventCreateWithFlags(&evFork,  cudaEventDisableTiming);
        cudaEventCreateWithFlags(&evRoot1, cudaEventDisableTiming);
        cudaEventCreateWithFlags(&evRoot2, cudaEventDisableTiming);
        cudaEventCreateWithFlags(&evRoot3, cudaEventDisableTiming);
        cudaEventCreateWithFlags(&evL1,    cudaEventDisableTiming);
        cudaEventCreateWithFlags(&evL2,    cudaEventDisableTiming);
    }

    // ---- layer 1: root-GEMM(x) on s2 || preproc + gather on stream 0 ----
    cudaEventRecord(evFork, 0);
    cudaStreamWaitEvent(s2, evFork, 0);
    k_gemm<<<gb, 256, SMEMSZ, s2>>>(x, 0, 1, Wo1, nullptr, N, 0, 0); // h0 = x@Wo1^T
    cudaEventRecord(evRoot1, s2);

    k_init<<<nb, 256>>>(N);
    k_detect<<<1, 1024>>>(eraw, E, 0);
    k_detect<<<1, 1024>>>(braw, N / 2, 1);
    k_edges<<<eb, 256>>>(eraw, E);
    k_batch<<<nb, 256>>>(braw, N, G);
    k_scan1<<<nsb, 1024>>>(N);
    k_scan2<<<1, 32>>>(nsb);
    k_scan3<<<nsb, 1024>>>(N);
    k_fill<<<eb, 256>>>(E);
    k_gather<<<gw, 256>>>(x, 0, N);

    cudaStreamWaitEvent(0, evRoot1, 0);
    k_gemm<<<gb, 256, SMEMSZ>>>(x, 3, 1, Wr1, br1, N, 1, 1);  // h0 += agg@Wr1^T + b, relu

    // ---- layer 2 ----
    cudaEventRecord(evL1, 0);
    cudaStreamWaitEvent(s2, evL1, 0);
    k_gemm<<<gb, 256, SMEMSZ, s2>>>(x, 1, 2, Wo2, nullptr, N, 0, 0); // h1 = h0@Wo2^T
    cudaEventRecord(evRoot2, s2);
    k_gather<<<gw, 256>>>(x, 1, N);                                   // agg = gather(h0)
    cudaStreamWaitEvent(0, evRoot2, 0);
    k_gemm<<<gb, 256, SMEMSZ>>>(x, 3, 2, Wr2, br2, N, 1, 1);          // h1 += agg@Wr2^T + b, relu

    // ---- layer 3 ----
    cudaEventRecord(evL2, 0);
    cudaStreamWaitEvent(s2, evL2, 0);
    k_gemm<<<gb, 256, SMEMSZ, s2>>>(x, 2, 1, Wo3, nullptr, N, 0, 0);  // h0 = h1@Wo3^T
    cudaEventRecord(evRoot3, s2);
    k_gather<<<gw, 256>>>(x, 2, N);                                   // agg = gather(h1)
    cudaStreamWaitEvent(0, evRoot3, 0);
    k_gemm<<<gb, 256, SMEMSZ>>>(x, 3, 1, Wr3, br3, N, 1, 0);          // h0 += agg@Wr3^T + b

    // ---- pool + mlp ----
    dim3 pg(G, DD / 32);
    k_pool<<<pg, 256>>>();
    k_mlp<<<1, 64>>>(W1, b1, W2, b2, out, G);
}

// round 6
// speedup vs baseline: 1.1328x; 1.0048x over previous
#include <cuda_runtime.h>

#define DD 128
#define MAXN 50000
#define MAXE 600000
#define GG 64

// ---------------- scratch (static device globals; no runtime allocation) ----
__device__ float g_agg[MAXN * DD];
__device__ float g_h0[MAXN * DD];
__device__ float g_h1[MAXN * DD];
__device__ int   g_deg[MAXN];
__device__ int   g_off[MAXN + 1];
__device__ int   g_cur[MAXN];
__device__ int   g_csr[MAXE];
__device__ int   g_src[MAXE];
__device__ int   g_dst[MAXE];
__device__ int   g_gstart[GG + 1];
__device__ float g_pool[GG * DD];
__device__ int   g_e32;       // 1 if edge_index is int32, 0 if int64
__device__ int   g_b32;       // 1 if batch is int32, 0 if int64
__device__ int   g_bsum[64];  // block partial sums for the scan

// ---------------- preprocessing ---------------------------------------------

__global__ void k_init(int N) {
    int i = blockIdx.x * blockDim.x + threadIdx.x;
    if (i < N) g_deg[i] = 0;
    if (i == 0) { g_e32 = 0; g_b32 = 0; }
}

// Strided sampling: int64 nonneg values have all odd 32-bit words zero.
// 1024 samples spread over the array; int32 data has nonzero odd words.
__global__ void k_detect(const int* __restrict__ raw, int npairs, int which) {
    long idx = ((long)threadIdx.x * npairs) >> 10;
    if (idx < npairs && raw[2 * idx + 1] != 0) {
        if (which) g_b32 = 1; else g_e32 = 1;
    }
}

// convert edges + degree histogram (fused)
__global__ void k_edges(const int* __restrict__ raw, int E) {
    int e = blockIdx.x * blockDim.x + threadIdx.x;
    if (e >= E) return;
    int s, d;
    if (g_e32) { s = raw[e];     d = raw[E + e]; }
    else       { s = raw[2 * e]; d = raw[2 * (E + e)]; }
    g_src[e] = s;
    g_dst[e] = d;
    atomicAdd(&g_deg[d], 1);
}

// convert batch + graph boundaries (fused; batch is sorted)
__global__ void k_batch(const int* __restrict__ raw, int N, int G) {
    int i = blockIdx.x * blockDim.x + threadIdx.x;
    if (i >= N) return;
    int b  = g_b32 ? raw[i] : raw[2 * i];
    int pb = (i == 0) ? -1 : (g_b32 ? raw[i - 1] : raw[2 * (i - 1)]);
    for (int g = pb + 1; g <= b; ++g) g_gstart[g] = i;
    if (i == N - 1)
        for (int g = b + 1; g <= G; ++g) g_gstart[g] = N;
}

// scan phase 1: per-1024-block reduction of g_deg -> g_bsum
__global__ void k_scan1(int N) {
    __shared__ int sw[32];
    int tid = threadIdx.x, lane = tid & 31, w = tid >> 5;
    int i = blockIdx.x * 1024 + tid;
    int v = (i < N) ? g_deg[i] : 0;
#pragma unroll
    for (int d = 16; d > 0; d >>= 1) v += __shfl_down_sync(0xffffffffu, v, d);
    if (lane == 0) sw[w] = v;
    __syncthreads();
    if (w == 0) {
        v = sw[lane];
#pragma unroll
        for (int d = 16; d > 0; d >>= 1) v += __shfl_down_sync(0xffffffffu, v, d);
        if (lane == 0) g_bsum[blockIdx.x] = v;
    }
}

// scan phase 2: exclusive scan of the (<=64) block sums, trivial serial
__global__ void k_scan2(int nsb) {
    if (threadIdx.x == 0) {
        int a = 0;
        for (int b = 0; b < nsb; ++b) { int t = g_bsum[b]; g_bsum[b] = a; a += t; }
    }
}

// scan phase 3: per-block inclusive scan + base -> g_off / g_cur
__global__ void k_scan3(int N) {
    __shared__ int sw[32];
    int tid = threadIdx.x, lane = tid & 31, w = tid >> 5;
    int i = blockIdx.x * 1024 + tid;
    int v = (i < N) ? g_deg[i] : 0;
    int x = v;
#pragma unroll
    for (int d = 1; d < 32; d <<= 1) {
        int t = __shfl_up_sync(0xffffffffu, x, d);
        if (lane >= d) x += t;
    }
    if (lane == 31) sw[w] = x;
    __syncthreads();
    if (w == 0) {
        int y = sw[lane];
#pragma unroll
        for (int d = 1; d < 32; d <<= 1) {
            int t = __shfl_up_sync(0xffffffffu, y, d);
            if (lane >= d) y += t;
        }
        sw[lane] = y;
    }
    __syncthreads();
    x += ((w > 0) ? sw[w - 1] : 0) + g_bsum[blockIdx.x];
    if (i < N) { g_off[i + 1] = x; g_cur[i] = x - v; }
    if (i == 0) g_off[0] = 0;
}

__global__ void k_fill(int E) {
    int e = blockIdx.x * blockDim.x + threadIdx.x;
    if (e >= E) return;
    int p = atomicAdd(&g_cur[g_dst[e]], 1);
    g_csr[p] = g_src[e];
}

// ---------------- layer kernels ---------------------------------------------

// One warp per node: sum h[src] over incoming edges, 2-edge unrolled.
__global__ void k_gather(const float* __restrict__ xin, int sel, int N) {
    int warp = (blockIdx.x * blockDim.x + threadIdx.x) >> 5;
    int lane = threadIdx.x & 31;
    if (warp >= N) return;
    const float* H = (sel == 0) ? xin : (sel == 1 ? g_h0 : g_h1);
    const float4* H4 = reinterpret_cast<const float4*>(H);
    int s = g_off[warp], e = g_off[warp + 1];
    float4 acc = make_float4(0.f, 0.f, 0.f, 0.f);
    int i = s;
    for (; i + 2 <= e; i += 2) {
        int s0 = g_csr[i], s1 = g_csr[i + 1];
        float4 v0 = H4[s0 * 32 + lane];
        float4 v1 = H4[s1 * 32 + lane];
        acc.x += v0.x + v1.x; acc.y += v0.y + v1.y;
        acc.z += v0.z + v1.z; acc.w += v0.w + v1.w;
    }
    if (i < e) {
        float4 v = H4[g_csr[i] * 32 + lane];
        acc.x += v.x; acc.y += v.y; acc.z += v.z; acc.w += v.w;
    }
    reinterpret_cast<float4*>(g_agg)[warp * 32 + lane] = acc;
}

// Single-W GEMM: out = A @ W^T (+bias) (+= existing) (relu), 128x128 tile,
// 256 threads, 8x8 micro, f32x2 packed FMA, double-buffered A staging.
// smem: Ws[128][132] k-major + As[2][16][132] => 84480 B => 2 CTAs/SM.
__global__ void __launch_bounds__(256, 2) k_gemm(
    const float* __restrict__ xin, int selIn, int selOut,
    const float* __restrict__ W, const float* __restrict__ bias,
    int N, int accumulate, int do_relu)
{
    extern __shared__ float sm[];
    float* Ws = sm;                 // [128][132] k-major: Ws[k*132+n]
    float* As = sm + 128 * 132;     // [2][16][132] k-major: As[buf][k][m]

    const int tid  = threadIdx.x;
    const int tm   = tid >> 4;
    const int tn   = tid & 15;
    const int row0 = blockIdx.x * 128;

    const float* Ain =
        (selIn == 0) ? xin : (selIn == 1 ? g_h0 : (selIn == 2 ? g_h1 : g_agg));
    float* Hout = (selOut == 1) ? g_h0 : g_h1;
    const float4* A4 = reinterpret_cast<const float4*>(Ain);

    // load W into smem, transposed to k-major
    for (int idx = tid; idx < 128 * 128; idx += 256) {
        int n = idx >> 7, k = idx & 127;
        Ws[k * 132 + n] = W[idx];
    }

    unsigned long long acc[8][4];
#pragma unroll
    for (int i = 0; i < 8; ++i)
#pragma unroll
        for (int j = 0; j < 4; ++j) acc[i][j] = 0ull;

    auto stage = [&](int buf, int c) {
        float* dst = As + buf * (16 * 132);
        int k0 = c * 16;
#pragma unroll
        for (int t = 0; t < 2; ++t) {
            int i = tid * 2 + t;
            int m = i >> 2, q = i & 3;
            int row = row0 + m;
            float4 v = make_float4(0.f, 0.f, 0.f, 0.f);
            if (row < N) v = A4[row * 32 + (k0 >> 2) + q];
            dst[(q * 4 + 0) * 132 + m] = v.x;
            dst[(q * 4 + 1) * 132 + m] = v.y;
            dst[(q * 4 + 2) * 132 + m] = v.z;
            dst[(q * 4 + 3) * 132 + m] = v.w;
        }
    };

    stage(0, 0);
    __syncthreads();

#pragma unroll 1
    for (int c = 0; c < 8; ++c) {
        int buf = c & 1;
        if (c < 7) stage(buf ^ 1, c + 1);   // prefetch next chunk
        const float* Wb = Ws + (c * 16) * 132 + tn * 8;
        const float* Ab = As + buf * (16 * 132) + tm * 8;
#pragma unroll
        for (int kk = 0; kk < 16; ++kk) {
            float a[8];
            *reinterpret_cast<float4*>(a)     = *reinterpret_cast<const float4*>(Ab + kk * 132);
            *reinterpret_cast<float4*>(a + 4) = *reinterpret_cast<const float4*>(Ab + kk * 132 + 4);
            ulonglong2 bA = *reinterpret_cast<const ulonglong2*>(Wb + kk * 132);
            ulonglong2 bB = *reinterpret_cast<const ulonglong2*>(Wb + kk * 132 + 4);
            unsigned long long b2[4] = { bA.x, bA.y, bB.x, bB.y };
#pragma unroll
            for (int i = 0; i < 8; ++i) {
                unsigned long long a2;
                asm("mov.b64 %0, {%1, %1};" : "=l"(a2) : "f"(a[i]));
#pragma unroll
                for (int j = 0; j < 4; ++j)
                    asm("fma.rn.f32x2 %0, %1, %2, %0;"
                        : "+l"(acc[i][j]) : "l"(a2), "l"(b2[j]));
            }
        }
        __syncthreads();
    }

    float bv[8];
    if (bias) {
        *reinterpret_cast<float4*>(bv)     = *reinterpret_cast<const float4*>(bias + tn * 8);
        *reinterpret_cast<float4*>(bv + 4) = *reinterpret_cast<const float4*>(bias + tn * 8 + 4);
    } else {
#pragma unroll
        for (int j = 0; j < 8; ++j) bv[j] = 0.f;
    }

#pragma unroll
    for (int i = 0; i < 8; ++i) {
        int row = row0 + tm * 8 + i;
        if (row >= N) continue;
        float o[8];
#pragma unroll
        for (int j = 0; j < 4; ++j) {
            float lo, hi;
            asm("mov.b64 {%0, %1}, %2;" : "=f"(lo), "=f"(hi) : "l"(acc[i][j]));
            o[2 * j]     = lo + bv[2 * j];
            o[2 * j + 1] = hi + bv[2 * j + 1];
        }
        float4* dst = reinterpret_cast<float4*>(Hout + (long)row * 128 + tn * 8);
        if (accumulate) {
            float4 p0 = dst[0], p1 = dst[1];
            o[0] += p0.x; o[1] += p0.y; o[2] += p0.z; o[3] += p0.w;
            o[4] += p1.x; o[5] += p1.y; o[6] += p1.z; o[7] += p1.w;
        }
        if (do_relu) {
#pragma unroll
            for (int j = 0; j < 8; ++j) o[j] = fmaxf(o[j], 0.f);
        }
        dst[0] = *reinterpret_cast<float4*>(o);
        dst[1] = *reinterpret_cast<float4*>(o + 4);
    }
}

// ---------------- pooling + MLP ---------------------------------------------

__global__ void k_pool() {
    int g     = blockIdx.x;
    int chunk = blockIdx.y;
    int lane  = threadIdx.x & 31;
    int grp   = threadIdx.x >> 5;
    int col   = chunk * 32 + lane;
    int s = g_gstart[g], e = g_gstart[g + 1];
    float m = -3.402823466e38f;
    for (int r = s + grp; r < e; r += 8)
        m = fmaxf(m, g_h0[(long)r * 128 + col]);
    __shared__ float smx[8][32];
    smx[grp][lane] = m;
    __syncthreads();
    if (grp == 0) {
#pragma unroll
        for (int i = 1; i < 8; ++i) m = fmaxf(m, smx[i][lane]);
        g_pool[g * 128 + col] = m;
    }
}

__global__ void k_mlp(const float* __restrict__ W1, const float* __restrict__ b1,
                      const float* __restrict__ W2, const float* __restrict__ b2,
                      float* __restrict__ out, int G) {
    int g = threadIdx.x;
    if (g >= G) return;
    float o = b2[0];
#pragma unroll
    for (int j = 0; j < 5; ++j) {
        float s = b1[j];
        for (int k = 0; k < DD; k += 4) {
            float4 p  = reinterpret_cast<const float4*>(g_pool + g * DD)[k >> 2];
            float4 ww = reinterpret_cast<const float4*>(W1 + j * DD)[k >> 2];
            s += p.x * ww.x + p.y * ww.y + p.z * ww.z + p.w * ww.w;
        }
        o += fmaxf(s, 0.f) * W2[j];
    }
    out[g] = o;
}

// ---------------- launch -----------------------------------------------------

extern "C" void kernel_launch(void* const* d_in, const int* in_sizes, int n_in,
                              void* d_out, int out_size) {
    const float* x    = (const float*)d_in[0];
    const int*   eraw = (const int*)d_in[1];
    const int*   braw = (const int*)d_in[2];
    const float* Wr1  = (const float*)d_in[3];
    const float* br1  = (const float*)d_in[4];
    const float* Wo1  = (const float*)d_in[5];
    const float* Wr2  = (const float*)d_in[6];
    const float* br2  = (const float*)d_in[7];
    const float* Wo2  = (const float*)d_in[8];
    const float* Wr3  = (const float*)d_in[9];
    const float* br3  = (const float*)d_in[10];
    const float* Wo3  = (const float*)d_in[11];
    const float* W1   = (const float*)d_in[12];
    const float* b1   = (const float*)d_in[13];
    const float* W2   = (const float*)d_in[14];
    const float* b2   = (const float*)d_in[15];
    float* out = (float*)d_out;

    const int N = in_sizes[0] / DD;
    const int E = in_sizes[1] / 2;
    const int G = out_size;

    const int nb  = (N + 255) / 256;
    const int eb  = (E + 255) / 256;
    const int nsb = (N + 1023) / 1024;
    const int gw  = (N + 7) / 8;
    const int gb  = (N + 127) / 128;

    const size_t SMEMSZ = (size_t)(128 * 132 + 2 * 16 * 132) * sizeof(float);
    cudaFuncSetAttribute(k_gemm, cudaFuncAttributeMaxDynamicSharedMemorySize,
                         (int)SMEMSZ);

    // Second stream + events, created once (outside capture on the first,
    // non-captured correctness call). Work is identical on every call.
    static cudaStream_t s2 = nullptr;
    static cudaEvent_t evFork, evRoot1, evRoot2, evRoot3, evL1, evL2;
    if (!s2) {
        cudaStreamCreateWithFlags(&s2, cudaStreamNonBlocking);
        cudaEventCreateWithFlags(&evFork,  cudaEventDisableTiming);
        cudaEventCreateWithFlags(&evRoot1, cudaEventDisableTiming);
        cudaEventCreateWithFlags(&evRoot2, cudaEventDisableTiming);
        cudaEventCreateWithFlags(&evRoot3, cudaEventDisableTiming);
        cudaEventCreateWithFlags(&evL1,    cudaEventDisableTiming);
        cudaEventCreateWithFlags(&evL2,    cudaEventDisableTiming);
    }

    // ---- layer 1: root-GEMM(x) on s2 || preproc + gather on stream 0 ----
    cudaEventRecord(evFork, 0);
    cudaStreamWaitEvent(s2, evFork, 0);
    k_gemm<<<gb, 256, SMEMSZ, s2>>>(x, 0, 1, Wo1, nullptr, N, 0, 0); // h0 = x@Wo1^T
    cudaEventRecord(evRoot1, s2);

    k_init<<<nb, 256>>>(N);
    k_detect<<<1, 1024>>>(eraw, E, 0);
    k_detect<<<1, 1024>>>(braw, N / 2, 1);
    k_edges<<<eb, 256>>>(eraw, E);
    k_batch<<<nb, 256>>>(braw, N, G);
    k_scan1<<<nsb, 1024>>>(N);
    k_scan2<<<1, 32>>>(nsb);
    k_scan3<<<nsb, 1024>>>(N);
    k_fill<<<eb, 256>>>(E);
    k_gather<<<gw, 256>>>(x, 0, N);

    cudaStreamWaitEvent(0, evRoot1, 0);
    k_gemm<<<gb, 256, SMEMSZ>>>(x, 3, 1, Wr1, br1, N, 1, 1);  // h0 += agg@Wr1^T + b, relu

    // ---- layer 2 ----
    cudaEventRecord(evL1, 0);
    cudaStreamWaitEvent(s2, evL1, 0);
    k_gemm<<<gb, 256, SMEMSZ, s2>>>(x, 1, 2, Wo2, nullptr, N, 0, 0); // h1 = h0@Wo2^T
    cudaEventRecord(evRoot2, s2);
    k_gather<<<gw, 256>>>(x, 1, N);                                   // agg = gather(h0)
    cudaStreamWaitEvent(0, evRoot2, 0);
    k_gemm<<<gb, 256, SMEMSZ>>>(x, 3, 2, Wr2, br2, N, 1, 1);          // h1 += agg@Wr2^T + b, relu

    // ---- layer 3 ----
    cudaEventRecord(evL2, 0);
    cudaStreamWaitEvent(s2, evL2, 0);
    k_gemm<<<gb, 256, SMEMSZ, s2>>>(x, 2, 1, Wo3, nullptr, N, 0, 0);  // h0 = h1@Wo3^T
    cudaEventRecord(evRoot3, s2);
    k_gather<<<gw, 256>>>(x, 2, N);                                   // agg = gather(h1)
    cudaStreamWaitEvent(0, evRoot3, 0);
    k_gemm<<<gb, 256, SMEMSZ>>>(x, 3, 1, Wr3, br3, N, 1, 0);          // h0 += agg@Wr3^T + b

    // ---- pool + mlp ----
    dim3 pg(G, DD / 32);
    k_pool<<<pg, 256>>>();
    k_mlp<<<1, 64>>>(W1, b1, W2, b2, out, G);
}